// round 11
// baseline (speedup 1.0000x reference)
#include <cuda_runtime.h>
#include <cuda_bf16.h>
#include <cuda_fp16.h>
#include <math.h>
#include <stdint.h>

// Problem constants (fixed instance)
#define NMAX   100000
#define EMAX   1600000
#define IN_DIM 256
#define HID    64      // HEADS*D1 = 8*8
#define HEADS  8
#define D1     8
#define NCLS   47
#define NC2P   48      // padded stride for layer-2 feature arrays
#define N2PAD  96      // padded output cols for gemm2 (2*47 -> 96)
#define NEG_SLOPE 0.2f

// ---------------- device scratch (static allocation; no cudaMalloc) ----------------
__device__ int   g_is64;
__device__ int   g_dst32[EMAX];
__device__ int   g_src_sorted[EMAX];
__device__ int   g_deg[NMAX];
__device__ int   g_rowptr[NMAX + 1];
__device__ int   g_cur[NMAX];
__device__ int   g_bsum[128];           // >= ceil(NMAX/1024)=98 block sums

__device__ __half g_fs1h[(size_t)NMAX * HID];    // fp16 src features, layer 1
__device__ float  g_fd1[(size_t)NMAX * HID];
__device__ float  g_h  [(size_t)NMAX * HID];
__device__ __half g_fs2h[(size_t)NMAX * NC2P];   // fp16 src features, layer 2
__device__ float  g_fd2[(size_t)NMAX * NC2P];

__device__ float g_Wc1[IN_DIM * 2 * HID];       // [256][128], pre-rounded to tf32
__device__ float g_bc1[2 * HID];
__device__ float g_Wc2p[HID * N2PAD];           // [64][96], tf32, cols 94-95 zero
__device__ float g_bc2[2 * NCLS];

__device__ __forceinline__ float lrelu(float x) { return x > 0.f ? x : NEG_SLOPE * x; }
__device__ __forceinline__ float elu(float x)   { return x > 0.f ? x : expm1f(x); }
__device__ __forceinline__ float tf32r(float x) {
    uint32_t r; asm("cvt.rna.tf32.f32 %0, %1;" : "=r"(r) : "f"(x));
    return __uint_as_float(r);
}

// ---------------- zero deg + index dtype detection (merged) ----------------
__global__ void zero_deg_kernel(const int* __restrict__ srcW, int N) {
    int v = blockIdx.x * blockDim.x + threadIdx.x;
    if (v < N) g_deg[v] = 0;
    if (blockIdx.x == 0 && threadIdx.x == 0) {
        int ok64 = 1;
        #pragma unroll
        for (int i = 1; i < 16; i += 2) if (srcW[i] != 0) ok64 = 0;
        g_is64 = ok64;
    }
}

__global__ void convert_hist_kernel(const void* __restrict__ dstRaw, int E) {
    int e = blockIdx.x * blockDim.x + threadIdx.x;
    if (e >= E) return;
    int d = g_is64 ? (int)((const long long*)dstRaw)[e] : ((const int*)dstRaw)[e];
    g_dst32[e] = d;
    atomicAdd(&g_deg[d], 1);
}

// ---------------- 3-phase multi-block exclusive scan of g_deg -> g_rowptr ----------------
__global__ void scan_phase1(int N) {
    __shared__ int sh[1024];
    int t = threadIdx.x;
    int i = blockIdx.x * 1024 + t;
    int v = (i < N) ? g_deg[i] : 0;
    sh[t] = v;
    __syncthreads();
    #pragma unroll
    for (int off = 1; off < 1024; off <<= 1) {
        int x = (t >= off) ? sh[t - off] : 0;
        __syncthreads();
        sh[t] += x;
        __syncthreads();
    }
    if (i < N) g_rowptr[i] = sh[t] - v;
    if (t == 1023) g_bsum[blockIdx.x] = sh[1023];
}

__global__ void scan_phase2(int nb, int N) {
    __shared__ int sh[128];
    int t = threadIdx.x;
    int v = (t < nb) ? g_bsum[t] : 0;
    sh[t] = v;
    __syncthreads();
    #pragma unroll
    for (int off = 1; off < 128; off <<= 1) {
        int x = (t >= off) ? sh[t - off] : 0;
        __syncthreads();
        sh[t] += x;
        __syncthreads();
    }
    if (t < nb) g_bsum[t] = sh[t] - v;
    if (t == 127) g_rowptr[N] = sh[127];
}

__global__ void scan_phase3(int N) {
    int i = blockIdx.x * blockDim.x + threadIdx.x;
    if (i < N) {
        int r = g_rowptr[i] + g_bsum[i >> 10];
        g_rowptr[i] = r;
        g_cur[i] = r;
    }
}

__global__ void scatter_kernel(const void* __restrict__ srcRaw, int E) {
    int e = blockIdx.x * blockDim.x + threadIdx.x;
    if (e >= E) return;
    int s = g_is64 ? (int)((const long long*)srcRaw)[e] : ((const int*)srcRaw)[e];
    int d = g_dst32[e];
    int p = atomicAdd(&g_cur[d], 1);
    g_src_sorted[p] = s;
}

// ---------------- weight packing (both layers, one kernel; tf32 pre-round) ----------------
__global__ void combine_kernel(const float* __restrict__ W1s, const float* __restrict__ b1s,
                               const float* __restrict__ W1d, const float* __restrict__ b1d,
                               const float* __restrict__ W2s, const float* __restrict__ b2s,
                               const float* __restrict__ W2d, const float* __restrict__ b2d) {
    int i = blockIdx.x * blockDim.x + threadIdx.x;
    if (i < IN_DIM * 2 * HID) {
        int k = i / (2 * HID), c = i % (2 * HID);
        float v = (c < HID) ? W1s[k * HID + c] : W1d[k * HID + (c - HID)];
        g_Wc1[i] = tf32r(v);
    }
    if (i < 2 * HID) g_bc1[i] = (i < HID) ? b1s[i] : b1d[i - HID];
    if (i < HID * N2PAD) {
        int k = i / N2PAD, c = i % N2PAD;
        float v = (c < NCLS) ? W2s[k * NCLS + c]
                : (c < 2 * NCLS) ? W2d[k * NCLS + (c - NCLS)] : 0.f;
        g_Wc2p[i] = tf32r(v);
    }
    if (i < 2 * NCLS) g_bc2[i] = (i < NCLS) ? b2s[i] : b2d[i - NCLS];
}

// ---------------- GEMM 1 (TF32 TC, register-prefetch pipeline) ----------------
__global__ void gemm1_tc_kernel(const float* __restrict__ x, int M) {
    __shared__ float As[128][36];
    __shared__ float Bs[32][136];
    int tid  = threadIdx.x;
    int lane = tid & 31;
    int warp = tid >> 5;
    int row0 = blockIdx.x * 128;
    int warpRow = warp * 16;
    int gid = lane >> 2;
    int tig = lane & 3;

    float c[16][4];
    #pragma unroll
    for (int j = 0; j < 16; ++j)
        #pragma unroll
        for (int q = 0; q < 4; ++q) c[j][q] = 0.f;

    float4 ra[4], rb[4];
    #pragma unroll
    for (int i = 0; i < 4; ++i) {
        int id = tid * 4 + i;
        int r = id >> 3, q = id & 7;
        int grow = row0 + r;
        ra[i] = (grow < M) ? *(const float4*)(x + (size_t)grow * IN_DIM + q * 4)
                           : make_float4(0.f, 0.f, 0.f, 0.f);
        int rB = id >> 5, qB = id & 31;
        rb[i] = *(const float4*)&g_Wc1[rB * 128 + qB * 4];
    }

    for (int chunk = 0; chunk < 8; ++chunk) {
        #pragma unroll
        for (int i = 0; i < 4; ++i) {
            int id = tid * 4 + i;
            int r = id >> 3, q = id & 7;
            float4 v = ra[i];
            v.x = tf32r(v.x); v.y = tf32r(v.y); v.z = tf32r(v.z); v.w = tf32r(v.w);
            *(float4*)&As[r][q * 4] = v;
            int rB = id >> 5, qB = id & 31;
            *(float4*)&Bs[rB][qB * 4] = rb[i];
        }
        __syncthreads();
        if (chunk < 7) {
            int k0 = (chunk + 1) * 32;
            #pragma unroll
            for (int i = 0; i < 4; ++i) {
                int id = tid * 4 + i;
                int r = id >> 3, q = id & 7;
                int grow = row0 + r;
                ra[i] = (grow < M) ? *(const float4*)(x + (size_t)grow * IN_DIM + k0 + q * 4)
                                   : make_float4(0.f, 0.f, 0.f, 0.f);
                int rB = id >> 5, qB = id & 31;
                rb[i] = *(const float4*)&g_Wc1[(k0 + rB) * 128 + qB * 4];
            }
        }
        #pragma unroll
        for (int kk = 0; kk < 32; kk += 8) {
            uint32_t a[4];
            a[0] = __float_as_uint(As[warpRow + gid    ][kk + tig    ]);
            a[1] = __float_as_uint(As[warpRow + gid + 8][kk + tig    ]);
            a[2] = __float_as_uint(As[warpRow + gid    ][kk + tig + 4]);
            a[3] = __float_as_uint(As[warpRow + gid + 8][kk + tig + 4]);
            #pragma unroll
            for (int j = 0; j < 16; ++j) {
                uint32_t b[2];
                b[0] = __float_as_uint(Bs[kk + tig    ][j * 8 + gid]);
                b[1] = __float_as_uint(Bs[kk + tig + 4][j * 8 + gid]);
                asm("mma.sync.aligned.m16n8k8.row.col.f32.tf32.tf32.f32 "
                    "{%0,%1,%2,%3}, {%4,%5,%6,%7}, {%8,%9}, {%0,%1,%2,%3};"
                    : "+f"(c[j][0]), "+f"(c[j][1]), "+f"(c[j][2]), "+f"(c[j][3])
                    : "r"(a[0]), "r"(a[1]), "r"(a[2]), "r"(a[3]),
                      "r"(b[0]), "r"(b[1]));
            }
        }
        __syncthreads();
    }
    int r0 = row0 + warpRow + gid;
    int r1 = r0 + 8;
    #pragma unroll
    for (int j = 0; j < 16; ++j) {
        int cb = j * 8 + tig * 2;
        float2 bv = *(const float2*)&g_bc1[cb];
        if (r0 < M) {
            float vx = c[j][0] + bv.x, vy = c[j][1] + bv.y;
            if (cb < HID)
                *(__half2*)&g_fs1h[(size_t)r0 * HID + cb] = __floats2half2_rn(vx, vy);
            else
                *(float2*)&g_fd1[(size_t)r0 * HID + cb - HID] = make_float2(vx, vy);
        }
        if (r1 < M) {
            float vx = c[j][2] + bv.x, vy = c[j][3] + bv.y;
            if (cb < HID)
                *(__half2*)&g_fs1h[(size_t)r1 * HID + cb] = __floats2half2_rn(vx, vy);
            else
                *(float2*)&g_fd1[(size_t)r1 * HID + cb - HID] = make_float2(vx, vy);
        }
    }
}

// ---------------- GEMM 2 (TF32 TC): h[M,64] @ Wc2p[64,96] -> fs2h|fd2 (stride 48) ----------------
__device__ __forceinline__ void g2_store(int row, int c, float v) {
    if (c >= 2 * NCLS) return;
    v += g_bc2[c];
    if (c < NCLS) g_fs2h[(size_t)row * NC2P + c] = __float2half_rn(v);
    else          g_fd2[(size_t)row * NC2P + (c - NCLS)] = v;
}

__global__ void gemm2_tc_kernel(int M) {
    __shared__ float As[128][36];
    __shared__ float Bs[32][104];
    int tid  = threadIdx.x;
    int lane = tid & 31;
    int warp = tid >> 5;
    int row0 = blockIdx.x * 128;
    int warpRow = warp * 16;
    int gid = lane >> 2;
    int tig = lane & 3;

    float c[12][4];
    #pragma unroll
    for (int j = 0; j < 12; ++j)
        #pragma unroll
        for (int q = 0; q < 4; ++q) c[j][q] = 0.f;

    float4 ra[4], rb[3];
    #pragma unroll
    for (int i = 0; i < 4; ++i) {
        int id = tid * 4 + i;
        int r = id >> 3, q = id & 7;
        int grow = row0 + r;
        ra[i] = (grow < M) ? *(const float4*)(g_h + (size_t)grow * HID + q * 4)
                           : make_float4(0.f, 0.f, 0.f, 0.f);
    }
    #pragma unroll
    for (int i = 0; i < 3; ++i) {
        int id = tid + i * 256;
        int r = id / 24, q = id % 24;
        rb[i] = *(const float4*)&g_Wc2p[r * N2PAD + q * 4];
    }

    #pragma unroll
    for (int chunk = 0; chunk < 2; ++chunk) {
        #pragma unroll
        for (int i = 0; i < 4; ++i) {
            int id = tid * 4 + i;
            int r = id >> 3, q = id & 7;
            float4 v = ra[i];
            v.x = tf32r(v.x); v.y = tf32r(v.y); v.z = tf32r(v.z); v.w = tf32r(v.w);
            *(float4*)&As[r][q * 4] = v;
        }
        #pragma unroll
        for (int i = 0; i < 3; ++i) {
            int id = tid + i * 256;
            int r = id / 24, q = id % 24;
            *(float4*)&Bs[r][q * 4] = rb[i];
        }
        __syncthreads();
        if (chunk == 0) {
            #pragma unroll
            for (int i = 0; i < 4; ++i) {
                int id = tid * 4 + i;
                int r = id >> 3, q = id & 7;
                int grow = row0 + r;
                ra[i] = (grow < M) ? *(const float4*)(g_h + (size_t)grow * HID + 32 + q * 4)
                                   : make_float4(0.f, 0.f, 0.f, 0.f);
            }
            #pragma unroll
            for (int i = 0; i < 3; ++i) {
                int id = tid + i * 256;
                int r = id / 24, q = id % 24;
                rb[i] = *(const float4*)&g_Wc2p[(32 + r) * N2PAD + q * 4];
            }
        }
        #pragma unroll
        for (int kk = 0; kk < 32; kk += 8) {
            uint32_t a[4];
            a[0] = __float_as_uint(As[warpRow + gid    ][kk + tig    ]);
            a[1] = __float_as_uint(As[warpRow + gid + 8][kk + tig    ]);
            a[2] = __float_as_uint(As[warpRow + gid    ][kk + tig + 4]);
            a[3] = __float_as_uint(As[warpRow + gid + 8][kk + tig + 4]);
            #pragma unroll
            for (int j = 0; j < 12; ++j) {
                uint32_t b[2];
                b[0] = __float_as_uint(Bs[kk + tig    ][j * 8 + gid]);
                b[1] = __float_as_uint(Bs[kk + tig + 4][j * 8 + gid]);
                asm("mma.sync.aligned.m16n8k8.row.col.f32.tf32.tf32.f32 "
                    "{%0,%1,%2,%3}, {%4,%5,%6,%7}, {%8,%9}, {%0,%1,%2,%3};"
                    : "+f"(c[j][0]), "+f"(c[j][1]), "+f"(c[j][2]), "+f"(c[j][3])
                    : "r"(a[0]), "r"(a[1]), "r"(a[2]), "r"(a[3]),
                      "r"(b[0]), "r"(b[1]));
            }
        }
        __syncthreads();
    }
    int r0 = row0 + warpRow + gid;
    int r1 = r0 + 8;
    #pragma unroll
    for (int j = 0; j < 12; ++j) {
        int cb = j * 8 + tig * 2;
        if (r0 < M) { g2_store(r0, cb, c[j][0]); g2_store(r0, cb + 1, c[j][1]); }
        if (r1 < M) { g2_store(r1, cb, c[j][2]); g2_store(r1, cb + 1, c[j][3]); }
    }
}

// ---------------- layer 1: HALF-warp per node, 4 dims/lane (fp16 gathers), head = 2 lanes ----------------
__global__ void layer1_kernel(int N, const float* __restrict__ attn1,
                              const float* __restrict__ bias1) {
    int gwarp = (blockIdx.x * blockDim.x + threadIdx.x) >> 5;
    int lane  = threadIdx.x & 31;
    int half  = lane >> 4;                   // 0 or 1
    int l16   = lane & 15;
    int w     = gwarp * 2 + half;
    if (w >= N) return;
    unsigned hmask = half ? 0xFFFF0000u : 0x0000FFFFu;
    int start = g_rowptr[w], end = g_rowptr[w + 1];
    int j0 = 4 * l16;                        // dims j0..j0+3 (head = l16>>1)

    float4 bv = *(const float4*)&bias1[j0];
    if (start == end) {
        float4 o = make_float4(elu(bv.x), elu(bv.y), elu(bv.z), elu(bv.w));
        *(float4*)&g_h[(size_t)w * HID + j0] = o;
        return;
    }
    float4 fdv = *(const float4*)&g_fd1[(size_t)w * HID + j0];
    float4 att = *(const float4*)&attn1[j0];

    float mx = -INFINITY, s = 0.f;
    float ax = 0.f, ay = 0.f, az = 0.f, aw = 0.f;

    for (int p = start; p < end; ++p) {
        int u = g_src_sorted[p];
        uint2 raw = *(const uint2*)&g_fs1h[(size_t)u * HID + j0];
        float2 f01 = __half22float2(*(__half2*)&raw.x);
        float2 f23 = __half22float2(*(__half2*)&raw.y);
        float t = lrelu(f01.x + fdv.x) * att.x + lrelu(f01.y + fdv.y) * att.y
                + lrelu(f23.x + fdv.z) * att.z + lrelu(f23.y + fdv.w) * att.w;
        t += __shfl_xor_sync(hmask, t, 1);   // head score (2 lanes per head)
        float ed = __expf(0.f - fabsf(t - mx));
        bool up = t > mx;
        float sc = up ? ed : 1.f;
        float wt = up ? 1.f : ed;
        mx = fmaxf(mx, t);
        s = fmaf(s, sc, wt);
        ax = fmaf(ax, sc, wt * f01.x);
        ay = fmaf(ay, sc, wt * f01.y);
        az = fmaf(az, sc, wt * f23.x);
        aw = fmaf(aw, sc, wt * f23.y);
    }
    float inv = 1.f / s;
    float4 o = make_float4(elu(ax * inv + bv.x), elu(ay * inv + bv.y),
                           elu(az * inv + bv.z), elu(aw * inv + bv.w));
    *(float4*)&g_h[(size_t)w * HID + j0] = o;
}

// ---------------- layer 2: warp/node, 2 classes per lane (fp16 gathers, stride 48) ----------------
__global__ void layer2_kernel(int N, const float* __restrict__ attn2,
                              const float* __restrict__ bias2,
                              float* __restrict__ out) {
    int w = (blockIdx.x * blockDim.x + threadIdx.x) >> 5;
    int lane = threadIdx.x & 31;
    if (w >= N) return;
    int start = g_rowptr[w], end = g_rowptr[w + 1];
    int j0 = 2 * lane;
    int off = j0 < 46 ? j0 : 46;                     // clamped, even -> aligned half2
    bool m0 = (j0 < NCLS), m1 = (j0 + 1 < NCLS);

    float b0 = m0 ? bias2[j0] : 0.f;
    float b1 = m1 ? bias2[j0 + 1] : 0.f;
    if (start == end) {
        if (m0) out[(size_t)w * NCLS + j0] = b0;
        if (m1) out[(size_t)w * NCLS + j0 + 1] = b1;
        return;
    }
    float2 fdr = *(const float2*)&g_fd2[(size_t)w * NC2P + off];
    float fdv0 = m0 ? fdr.x : 0.f;
    float fdv1 = m1 ? fdr.y : 0.f;
    float att0 = m0 ? attn2[j0] : 0.f;
    float att1 = m1 ? attn2[j0 + 1] : 0.f;

    float mx = -INFINITY, s = 0.f;
    float acc0 = 0.f, acc1 = 0.f;

    for (int p = start; p < end; ++p) {
        int u = g_src_sorted[p];
        uint32_t raw = *(const uint32_t*)&g_fs2h[(size_t)u * NC2P + off];
        float2 fr = __half22float2(*(__half2*)&raw);
        float f0 = m0 ? fr.x : 0.f;
        float f1 = m1 ? fr.y : 0.f;
        float t = lrelu(f0 + fdv0) * att0 + lrelu(f1 + fdv1) * att1;
        t += __shfl_xor_sync(0xffffffffu, t, 1);
        t += __shfl_xor_sync(0xffffffffu, t, 2);
        t += __shfl_xor_sync(0xffffffffu, t, 4);
        t += __shfl_xor_sync(0xffffffffu, t, 8);
        t += __shfl_xor_sync(0xffffffffu, t, 16);
        float ed = __expf(0.f - fabsf(t - mx));
        bool up = t > mx;
        float sc = up ? ed : 1.f;
        float wt = up ? 1.f : ed;
        mx = fmaxf(mx, t);
        s = fmaf(s, sc, wt);
        acc0 = fmaf(acc0, sc, wt * f0);
        acc1 = fmaf(acc1, sc, wt * f1);
    }
    float inv = 1.f / s;
    if (m0) out[(size_t)w * NCLS + j0]     = acc0 * inv + b0;
    if (m1) out[(size_t)w * NCLS + j0 + 1] = acc1 * inv + b1;
}

// ---------------- launch ----------------
extern "C" void kernel_launch(void* const* d_in, const int* in_sizes, int n_in,
                              void* d_out, int out_size) {
    const float* x      = (const float*)d_in[0];
    const void*  srcRaw = d_in[1];
    const void*  dstRaw = d_in[2];
    const float* W1s = (const float*)d_in[3];
    const float* b1s = (const float*)d_in[4];
    const float* W1d = (const float*)d_in[5];
    const float* b1d = (const float*)d_in[6];
    const float* attn1 = (const float*)d_in[7];
    const float* bias1 = (const float*)d_in[8];
    const float* W2s = (const float*)d_in[9];
    const float* b2s = (const float*)d_in[10];
    const float* W2d = (const float*)d_in[11];
    const float* b2d = (const float*)d_in[12];
    const float* attn2 = (const float*)d_in[13];
    const float* bias2 = (const float*)d_in[14];
    float* out = (float*)d_out;

    int N = in_sizes[0] / IN_DIM;   // 100000
    int E = in_sizes[1];            // 1600000
    int nb = (N + 1023) >> 10;      // scan blocks (98)

    zero_deg_kernel<<<(N + 255) / 256, 256>>>((const int*)srcRaw, N);
    convert_hist_kernel<<<(E + 255) / 256, 256>>>(dstRaw, E);
    scan_phase1<<<nb, 1024>>>(N);
    scan_phase2<<<1, 128>>>(nb, N);
    scan_phase3<<<(N + 255) / 256, 256>>>(N);
    scatter_kernel<<<(E + 255) / 256, 256>>>(srcRaw, E);

    combine_kernel<<<(IN_DIM * 2 * HID + 255) / 256, 256>>>(W1s, b1s, W1d, b1d,
                                                            W2s, b2s, W2d, b2d);

    gemm1_tc_kernel<<<(N + 127) / 128, 256>>>(x, N);
    layer1_kernel<<<(N + 15) / 16, 256>>>(N, attn1, bias1);
    gemm2_tc_kernel<<<(N + 127) / 128, 256>>>(N);
    layer2_kernel<<<(N + 7) / 8, 256>>>(N, attn2, bias2, out);
}

// round 12
// speedup vs baseline: 1.0570x; 1.0570x over previous
#include <cuda_runtime.h>
#include <cuda_bf16.h>
#include <math.h>
#include <stdint.h>

// Problem constants (fixed instance)
#define NMAX   100000
#define EMAX   1600000
#define IN_DIM 256
#define HID    64      // HEADS*D1 = 8*8
#define HEADS  8
#define D1     8
#define NCLS   47
#define NC2P   48      // padded stride for layer-2 feature arrays
#define N2PAD  96      // padded output cols for gemm2 (2*47 -> 96)
#define NEG_SLOPE 0.2f

// ---------------- device scratch (static allocation; no cudaMalloc) ----------------
__device__ int   g_is64;
__device__ int   g_dst32[EMAX];
__device__ int   g_src_sorted[EMAX];
__device__ int   g_deg[NMAX];
__device__ int   g_rowptr[NMAX + 1];
__device__ int   g_cur[NMAX];
__device__ int   g_bsum[128];           // >= ceil(NMAX/1024)=98 block sums

__device__ float g_fs1[(size_t)NMAX * HID];
__device__ float g_fd1[(size_t)NMAX * HID];
__device__ float g_h  [(size_t)NMAX * HID];
__device__ float g_fs2[(size_t)NMAX * NC2P];
__device__ float g_fd2[(size_t)NMAX * NC2P];

__device__ float g_Wc1[IN_DIM * 2 * HID];       // [256][128], pre-rounded to tf32
__device__ float g_bc1[2 * HID];
__device__ float g_Wc2p[HID * N2PAD];           // [64][96], tf32, cols 94-95 zero
__device__ float g_bc2[2 * NCLS];

__device__ __forceinline__ float lrelu(float x) { return x > 0.f ? x : NEG_SLOPE * x; }
__device__ __forceinline__ float elu(float x)   { return x > 0.f ? x : expm1f(x); }
__device__ __forceinline__ float tf32r(float x) {
    uint32_t r; asm("cvt.rna.tf32.f32 %0, %1;" : "=r"(r) : "f"(x));
    return __uint_as_float(r);
}

// ---------------- fused: weight packing + deg zero + index dtype detection ----------------
__global__ void combine_zero_kernel(const float* __restrict__ W1s, const float* __restrict__ b1s,
                                    const float* __restrict__ W1d, const float* __restrict__ b1d,
                                    const float* __restrict__ W2s, const float* __restrict__ b2s,
                                    const float* __restrict__ W2d, const float* __restrict__ b2d,
                                    const int* __restrict__ srcW, int N) {
    int i = blockIdx.x * blockDim.x + threadIdx.x;
    if (i < N) g_deg[i] = 0;
    if (i < IN_DIM * 2 * HID) {
        int k = i / (2 * HID), c = i % (2 * HID);
        float v = (c < HID) ? W1s[k * HID + c] : W1d[k * HID + (c - HID)];
        g_Wc1[i] = tf32r(v);
    }
    if (i < 2 * HID) g_bc1[i] = (i < HID) ? b1s[i] : b1d[i - HID];
    if (i < HID * N2PAD) {
        int k = i / N2PAD, c = i % N2PAD;
        float v = (c < NCLS) ? W2s[k * NCLS + c]
                : (c < 2 * NCLS) ? W2d[k * NCLS + (c - NCLS)] : 0.f;
        g_Wc2p[i] = tf32r(v);
    }
    if (i < 2 * NCLS) g_bc2[i] = (i < NCLS) ? b2s[i] : b2d[i - NCLS];
    if (i == 0) {
        int ok64 = 1;
        #pragma unroll
        for (int q = 1; q < 16; q += 2) if (srcW[q] != 0) ok64 = 0;
        g_is64 = ok64;
    }
}

__global__ void convert_hist_kernel(const void* __restrict__ dstRaw, int E) {
    int e = blockIdx.x * blockDim.x + threadIdx.x;
    if (e >= E) return;
    int d = g_is64 ? (int)((const long long*)dstRaw)[e] : ((const int*)dstRaw)[e];
    g_dst32[e] = d;
    atomicAdd(&g_deg[d], 1);
}

// ---------------- 3-phase multi-block exclusive scan of g_deg -> g_rowptr ----------------
__global__ void scan_phase1(int N) {
    __shared__ int sh[1024];
    int t = threadIdx.x;
    int i = blockIdx.x * 1024 + t;
    int v = (i < N) ? g_deg[i] : 0;
    sh[t] = v;
    __syncthreads();
    #pragma unroll
    for (int off = 1; off < 1024; off <<= 1) {
        int x = (t >= off) ? sh[t - off] : 0;
        __syncthreads();
        sh[t] += x;
        __syncthreads();
    }
    if (i < N) g_rowptr[i] = sh[t] - v;
    if (t == 1023) g_bsum[blockIdx.x] = sh[1023];
}

__global__ void scan_phase2(int nb, int N) {
    __shared__ int sh[128];
    int t = threadIdx.x;
    int v = (t < nb) ? g_bsum[t] : 0;
    sh[t] = v;
    __syncthreads();
    #pragma unroll
    for (int off = 1; off < 128; off <<= 1) {
        int x = (t >= off) ? sh[t - off] : 0;
        __syncthreads();
        sh[t] += x;
        __syncthreads();
    }
    if (t < nb) g_bsum[t] = sh[t] - v;
    if (t == 127) g_rowptr[N] = sh[127];
}

__global__ void scan_phase3(int N) {
    int i = blockIdx.x * blockDim.x + threadIdx.x;
    if (i < N) {
        int r = g_rowptr[i] + g_bsum[i >> 10];
        g_rowptr[i] = r;
        g_cur[i] = r;
    }
}

__global__ void scatter_kernel(const void* __restrict__ srcRaw, int E) {
    int e = blockIdx.x * blockDim.x + threadIdx.x;
    if (e >= E) return;
    int s = g_is64 ? (int)((const long long*)srcRaw)[e] : ((const int*)srcRaw)[e];
    int d = g_dst32[e];
    int p = atomicAdd(&g_cur[d], 1);
    g_src_sorted[p] = s;
}

// ---------------- GEMM 1 (TF32 TC, 64x32 warp tiles, register-prefetch) ----------------
// 256 threads = 8 warps as 2(M) x 4(N); block tile 128x128; warp tile 64x32.
__global__ void gemm1_tc_kernel(const float* __restrict__ x, int M) {
    __shared__ float As[128][36];
    __shared__ float Bs[32][136];
    int tid  = threadIdx.x;
    int lane = tid & 31;
    int warp = tid >> 5;
    int row0 = blockIdx.x * 128;
    int mRow = (warp >> 2) * 64;     // 0 or 64
    int nCol = (warp & 3) * 32;      // 0,32,64,96
    int gid = lane >> 2;
    int tig = lane & 3;

    float c[4][4][4];
    #pragma unroll
    for (int i = 0; i < 4; ++i)
        #pragma unroll
        for (int j = 0; j < 4; ++j)
            #pragma unroll
            for (int q = 0; q < 4; ++q) c[i][j][q] = 0.f;

    float4 ra[4], rb[4];
    #pragma unroll
    for (int i = 0; i < 4; ++i) {
        int id = tid * 4 + i;
        int r = id >> 3, q = id & 7;
        int grow = row0 + r;
        ra[i] = (grow < M) ? *(const float4*)(x + (size_t)grow * IN_DIM + q * 4)
                           : make_float4(0.f, 0.f, 0.f, 0.f);
        int rB = id >> 5, qB = id & 31;
        rb[i] = *(const float4*)&g_Wc1[rB * 128 + qB * 4];
    }

    for (int chunk = 0; chunk < 8; ++chunk) {
        #pragma unroll
        for (int i = 0; i < 4; ++i) {
            int id = tid * 4 + i;
            int r = id >> 3, q = id & 7;
            float4 v = ra[i];
            v.x = tf32r(v.x); v.y = tf32r(v.y); v.z = tf32r(v.z); v.w = tf32r(v.w);
            *(float4*)&As[r][q * 4] = v;
            int rB = id >> 5, qB = id & 31;
            *(float4*)&Bs[rB][qB * 4] = rb[i];
        }
        __syncthreads();
        if (chunk < 7) {
            int k0 = (chunk + 1) * 32;
            #pragma unroll
            for (int i = 0; i < 4; ++i) {
                int id = tid * 4 + i;
                int r = id >> 3, q = id & 7;
                int grow = row0 + r;
                ra[i] = (grow < M) ? *(const float4*)(x + (size_t)grow * IN_DIM + k0 + q * 4)
                                   : make_float4(0.f, 0.f, 0.f, 0.f);
                int rB = id >> 5, qB = id & 31;
                rb[i] = *(const float4*)&g_Wc1[(k0 + rB) * 128 + qB * 4];
            }
        }
        #pragma unroll
        for (int kk = 0; kk < 32; kk += 8) {
            uint32_t a[4][4];
            #pragma unroll
            for (int i = 0; i < 4; ++i) {
                int rr = mRow + i * 16;
                a[i][0] = __float_as_uint(As[rr + gid    ][kk + tig    ]);
                a[i][1] = __float_as_uint(As[rr + gid + 8][kk + tig    ]);
                a[i][2] = __float_as_uint(As[rr + gid    ][kk + tig + 4]);
                a[i][3] = __float_as_uint(As[rr + gid + 8][kk + tig + 4]);
            }
            #pragma unroll
            for (int j = 0; j < 4; ++j) {
                uint32_t b[2];
                b[0] = __float_as_uint(Bs[kk + tig    ][nCol + j * 8 + gid]);
                b[1] = __float_as_uint(Bs[kk + tig + 4][nCol + j * 8 + gid]);
                #pragma unroll
                for (int i = 0; i < 4; ++i) {
                    asm("mma.sync.aligned.m16n8k8.row.col.f32.tf32.tf32.f32 "
                        "{%0,%1,%2,%3}, {%4,%5,%6,%7}, {%8,%9}, {%0,%1,%2,%3};"
                        : "+f"(c[i][j][0]), "+f"(c[i][j][1]), "+f"(c[i][j][2]), "+f"(c[i][j][3])
                        : "r"(a[i][0]), "r"(a[i][1]), "r"(a[i][2]), "r"(a[i][3]),
                          "r"(b[0]), "r"(b[1]));
                }
            }
        }
        __syncthreads();
    }
    #pragma unroll
    for (int i = 0; i < 4; ++i) {
        int r0 = row0 + mRow + i * 16 + gid;
        int r1 = r0 + 8;
        #pragma unroll
        for (int j = 0; j < 4; ++j) {
            int cb = nCol + j * 8 + tig * 2;
            float2 bv = *(const float2*)&g_bc1[cb];
            if (r0 < M) {
                float2 v = make_float2(c[i][j][0] + bv.x, c[i][j][1] + bv.y);
                if (cb < HID) *(float2*)&g_fs1[(size_t)r0 * HID + cb] = v;
                else          *(float2*)&g_fd1[(size_t)r0 * HID + cb - HID] = v;
            }
            if (r1 < M) {
                float2 v = make_float2(c[i][j][2] + bv.x, c[i][j][3] + bv.y);
                if (cb < HID) *(float2*)&g_fs1[(size_t)r1 * HID + cb] = v;
                else          *(float2*)&g_fd1[(size_t)r1 * HID + cb - HID] = v;
            }
        }
    }
}

// ---------------- GEMM 2 (TF32 TC): h[M,64] @ Wc2p[64,96] -> fs2|fd2 (stride 48) ----------------
__device__ __forceinline__ void g2_store(int row, int c, float v) {
    if (c >= 2 * NCLS) return;
    v += g_bc2[c];
    if (c < NCLS) g_fs2[(size_t)row * NC2P + c] = v;
    else          g_fd2[(size_t)row * NC2P + (c - NCLS)] = v;
}

__global__ void gemm2_tc_kernel(int M) {
    __shared__ float As[128][36];
    __shared__ float Bs[32][104];
    int tid  = threadIdx.x;
    int lane = tid & 31;
    int warp = tid >> 5;
    int row0 = blockIdx.x * 128;
    int warpRow = warp * 16;
    int gid = lane >> 2;
    int tig = lane & 3;

    float c[12][4];
    #pragma unroll
    for (int j = 0; j < 12; ++j)
        #pragma unroll
        for (int q = 0; q < 4; ++q) c[j][q] = 0.f;

    float4 ra[4], rb[3];
    #pragma unroll
    for (int i = 0; i < 4; ++i) {
        int id = tid * 4 + i;
        int r = id >> 3, q = id & 7;
        int grow = row0 + r;
        ra[i] = (grow < M) ? *(const float4*)(g_h + (size_t)grow * HID + q * 4)
                           : make_float4(0.f, 0.f, 0.f, 0.f);
    }
    #pragma unroll
    for (int i = 0; i < 3; ++i) {
        int id = tid + i * 256;
        int r = id / 24, q = id % 24;
        rb[i] = *(const float4*)&g_Wc2p[r * N2PAD + q * 4];
    }

    #pragma unroll
    for (int chunk = 0; chunk < 2; ++chunk) {
        #pragma unroll
        for (int i = 0; i < 4; ++i) {
            int id = tid * 4 + i;
            int r = id >> 3, q = id & 7;
            float4 v = ra[i];
            v.x = tf32r(v.x); v.y = tf32r(v.y); v.z = tf32r(v.z); v.w = tf32r(v.w);
            *(float4*)&As[r][q * 4] = v;
        }
        #pragma unroll
        for (int i = 0; i < 3; ++i) {
            int id = tid + i * 256;
            int r = id / 24, q = id % 24;
            *(float4*)&Bs[r][q * 4] = rb[i];
        }
        __syncthreads();
        if (chunk == 0) {
            #pragma unroll
            for (int i = 0; i < 4; ++i) {
                int id = tid * 4 + i;
                int r = id >> 3, q = id & 7;
                int grow = row0 + r;
                ra[i] = (grow < M) ? *(const float4*)(g_h + (size_t)grow * HID + 32 + q * 4)
                                   : make_float4(0.f, 0.f, 0.f, 0.f);
            }
            #pragma unroll
            for (int i = 0; i < 3; ++i) {
                int id = tid + i * 256;
                int r = id / 24, q = id % 24;
                rb[i] = *(const float4*)&g_Wc2p[(32 + r) * N2PAD + q * 4];
            }
        }
        #pragma unroll
        for (int kk = 0; kk < 32; kk += 8) {
            uint32_t a[4];
            a[0] = __float_as_uint(As[warpRow + gid    ][kk + tig    ]);
            a[1] = __float_as_uint(As[warpRow + gid + 8][kk + tig    ]);
            a[2] = __float_as_uint(As[warpRow + gid    ][kk + tig + 4]);
            a[3] = __float_as_uint(As[warpRow + gid + 8][kk + tig + 4]);
            #pragma unroll
            for (int j = 0; j < 12; ++j) {
                uint32_t b[2];
                b[0] = __float_as_uint(Bs[kk + tig    ][j * 8 + gid]);
                b[1] = __float_as_uint(Bs[kk + tig + 4][j * 8 + gid]);
                asm("mma.sync.aligned.m16n8k8.row.col.f32.tf32.tf32.f32 "
                    "{%0,%1,%2,%3}, {%4,%5,%6,%7}, {%8,%9}, {%0,%1,%2,%3};"
                    : "+f"(c[j][0]), "+f"(c[j][1]), "+f"(c[j][2]), "+f"(c[j][3])
                    : "r"(a[0]), "r"(a[1]), "r"(a[2]), "r"(a[3]),
                      "r"(b[0]), "r"(b[1]));
            }
        }
        __syncthreads();
    }
    int r0 = row0 + warpRow + gid;
    int r1 = r0 + 8;
    #pragma unroll
    for (int j = 0; j < 12; ++j) {
        int cb = j * 8 + tig * 2;
        if (r0 < M) { g2_store(r0, cb, c[j][0]); g2_store(r0, cb + 1, c[j][1]); }
        if (r1 < M) { g2_store(r1, cb, c[j][2]); g2_store(r1, cb + 1, c[j][3]); }
    }
}

// ---------------- layer 1: HALF-warp per node, 4 dims/lane (float4), head = 2 lanes ----------------
__global__ void layer1_kernel(int N, const float* __restrict__ attn1,
                              const float* __restrict__ bias1) {
    int gwarp = (blockIdx.x * blockDim.x + threadIdx.x) >> 5;
    int lane  = threadIdx.x & 31;
    int half  = lane >> 4;                   // 0 or 1
    int l16   = lane & 15;
    int w     = gwarp * 2 + half;
    if (w >= N) return;
    unsigned hmask = half ? 0xFFFF0000u : 0x0000FFFFu;
    int start = g_rowptr[w], end = g_rowptr[w + 1];
    int j0 = 4 * l16;                        // dims j0..j0+3 (head = l16>>1)

    float4 bv = *(const float4*)&bias1[j0];
    if (start == end) {
        float4 o = make_float4(elu(bv.x), elu(bv.y), elu(bv.z), elu(bv.w));
        *(float4*)&g_h[(size_t)w * HID + j0] = o;
        return;
    }
    float4 fdv = *(const float4*)&g_fd1[(size_t)w * HID + j0];
    float4 att = *(const float4*)&attn1[j0];

    float mx = -INFINITY, s = 0.f;
    float ax = 0.f, ay = 0.f, az = 0.f, aw = 0.f;

    for (int p = start; p < end; ++p) {
        int u = g_src_sorted[p];
        float4 f = *(const float4*)&g_fs1[(size_t)u * HID + j0];
        float t = lrelu(f.x + fdv.x) * att.x + lrelu(f.y + fdv.y) * att.y
                + lrelu(f.z + fdv.z) * att.z + lrelu(f.w + fdv.w) * att.w;
        t += __shfl_xor_sync(hmask, t, 1);   // head score (2 lanes per head)
        float ed = __expf(0.f - fabsf(t - mx));
        bool up = t > mx;
        float sc = up ? ed : 1.f;
        float wt = up ? 1.f : ed;
        mx = fmaxf(mx, t);
        s = fmaf(s, sc, wt);
        ax = fmaf(ax, sc, wt * f.x);
        ay = fmaf(ay, sc, wt * f.y);
        az = fmaf(az, sc, wt * f.z);
        aw = fmaf(aw, sc, wt * f.w);
    }
    float inv = 1.f / s;
    float4 o = make_float4(elu(ax * inv + bv.x), elu(ay * inv + bv.y),
                           elu(az * inv + bv.z), elu(aw * inv + bv.w));
    *(float4*)&g_h[(size_t)w * HID + j0] = o;
}

// ---------------- layer 2: warp/node, 2 classes per lane (padded stride 48) ----------------
__global__ void layer2_kernel(int N, const float* __restrict__ attn2,
                              const float* __restrict__ bias2,
                              float* __restrict__ out) {
    int w = (blockIdx.x * blockDim.x + threadIdx.x) >> 5;
    int lane = threadIdx.x & 31;
    if (w >= N) return;
    int start = g_rowptr[w], end = g_rowptr[w + 1];
    int j0 = 2 * lane;
    int off = j0 < 46 ? j0 : 46;                     // clamped, even -> aligned float2
    bool m0 = (j0 < NCLS), m1 = (j0 + 1 < NCLS);

    float b0 = m0 ? bias2[j0] : 0.f;
    float b1 = m1 ? bias2[j0 + 1] : 0.f;
    if (start == end) {
        if (m0) out[(size_t)w * NCLS + j0] = b0;
        if (m1) out[(size_t)w * NCLS + j0 + 1] = b1;
        return;
    }
    float2 fdr = *(const float2*)&g_fd2[(size_t)w * NC2P + off];
    float fdv0 = m0 ? fdr.x : 0.f;
    float fdv1 = m1 ? fdr.y : 0.f;
    float att0 = m0 ? attn2[j0] : 0.f;
    float att1 = m1 ? attn2[j0 + 1] : 0.f;

    float mx = -INFINITY, s = 0.f;
    float acc0 = 0.f, acc1 = 0.f;

    for (int p = start; p < end; ++p) {
        int u = g_src_sorted[p];
        float2 fr = *(const float2*)&g_fs2[(size_t)u * NC2P + off];
        float f0 = m0 ? fr.x : 0.f;
        float f1 = m1 ? fr.y : 0.f;
        float t = lrelu(f0 + fdv0) * att0 + lrelu(f1 + fdv1) * att1;
        t += __shfl_xor_sync(0xffffffffu, t, 1);
        t += __shfl_xor_sync(0xffffffffu, t, 2);
        t += __shfl_xor_sync(0xffffffffu, t, 4);
        t += __shfl_xor_sync(0xffffffffu, t, 8);
        t += __shfl_xor_sync(0xffffffffu, t, 16);
        float ed = __expf(0.f - fabsf(t - mx));
        bool up = t > mx;
        float sc = up ? ed : 1.f;
        float wt = up ? 1.f : ed;
        mx = fmaxf(mx, t);
        s = fmaf(s, sc, wt);
        acc0 = fmaf(acc0, sc, wt * f0);
        acc1 = fmaf(acc1, sc, wt * f1);
    }
    float inv = 1.f / s;
    if (m0) out[(size_t)w * NCLS + j0]     = acc0 * inv + b0;
    if (m1) out[(size_t)w * NCLS + j0 + 1] = acc1 * inv + b1;
}

// ---------------- launch ----------------
extern "C" void kernel_launch(void* const* d_in, const int* in_sizes, int n_in,
                              void* d_out, int out_size) {
    const float* x      = (const float*)d_in[0];
    const void*  srcRaw = d_in[1];
    const void*  dstRaw = d_in[2];
    const float* W1s = (const float*)d_in[3];
    const float* b1s = (const float*)d_in[4];
    const float* W1d = (const float*)d_in[5];
    const float* b1d = (const float*)d_in[6];
    const float* attn1 = (const float*)d_in[7];
    const float* bias1 = (const float*)d_in[8];
    const float* W2s = (const float*)d_in[9];
    const float* b2s = (const float*)d_in[10];
    const float* W2d = (const float*)d_in[11];
    const float* b2d = (const float*)d_in[12];
    const float* attn2 = (const float*)d_in[13];
    const float* bias2 = (const float*)d_in[14];
    float* out = (float*)d_out;

    int N = in_sizes[0] / IN_DIM;   // 100000
    int E = in_sizes[1];            // 1600000
    int nb = (N + 1023) >> 10;      // scan blocks (98)

    // #1: fused combine + zero_deg + detect (covers N range)
    combine_zero_kernel<<<(N + 255) / 256, 256>>>(W1s, b1s, W1d, b1d,
                                                  W2s, b2s, W2d, b2d,
                                                  (const int*)srcRaw, N);
    // #2
    convert_hist_kernel<<<(E + 255) / 256, 256>>>(dstRaw, E);
    // #3
    scan_phase1<<<nb, 1024>>>(N);
    // #4  <- ncu-captured launch: gemm1 (independent of scan chain)
    gemm1_tc_kernel<<<(N + 127) / 128, 256>>>(x, N);
    // #5..#7: finish CSR build
    scan_phase2<<<1, 128>>>(nb, N);
    scan_phase3<<<(N + 255) / 256, 256>>>(N);
    scatter_kernel<<<(E + 255) / 256, 256>>>(srcRaw, E);
    // #8..#10
    layer1_kernel<<<(N + 15) / 16, 256>>>(N, attn1, bias1);
    gemm2_tc_kernel<<<(N + 127) / 128, 256>>>(N);
    layer2_kernel<<<(N + 7) / 8, 256>>>(N, attn2, bias2, out);
}

// round 13
// speedup vs baseline: 1.0628x; 1.0055x over previous
#include <cuda_runtime.h>
#include <cuda_bf16.h>
#include <math.h>
#include <stdint.h>

// Problem constants (fixed instance)
#define NMAX   100000
#define EMAX   1600000
#define IN_DIM 256
#define HID    64      // HEADS*D1 = 8*8
#define HEADS  8
#define D1     8
#define NCLS   47
#define NC2P   48      // padded stride for layer-2 feature arrays
#define N2PAD  96      // padded output cols for gemm2 (2*47 -> 96)
#define NEG_SLOPE 0.2f

// ---------------- device scratch (static allocation; no cudaMalloc) ----------------
__device__ int   g_is64;
__device__ int   g_dst32[EMAX];
__device__ int   g_src_sorted[EMAX];
__device__ int   g_deg[NMAX];
__device__ int   g_rowptr[NMAX + 1];
__device__ int   g_cur[NMAX];
__device__ int   g_bsum[128];           // >= ceil(NMAX/1024)=98 block sums

__device__ float g_fs1[(size_t)NMAX * HID];
__device__ float g_fd1[(size_t)NMAX * HID];
__device__ float g_h  [(size_t)NMAX * HID];
__device__ float g_fs2[(size_t)NMAX * NC2P];
__device__ float g_fd2[(size_t)NMAX * NC2P];

__device__ float g_Wc1[IN_DIM * 2 * HID];       // [256][128], pre-rounded to tf32
__device__ float g_bc1[2 * HID];
__device__ float g_Wc2p[HID * N2PAD];           // [64][96], tf32, cols 94-95 zero
__device__ float g_bc2[2 * NCLS];

__device__ __forceinline__ float lrelu(float x) { return x > 0.f ? x : NEG_SLOPE * x; }
__device__ __forceinline__ float elu(float x)   { return x > 0.f ? x : expm1f(x); }
__device__ __forceinline__ float tf32r(float x) {
    uint32_t r; asm("cvt.rna.tf32.f32 %0, %1;" : "=r"(r) : "f"(x));
    return __uint_as_float(r);
}

// ---------------- fused: weight packing + deg zero + index dtype detection ----------------
__global__ void combine_zero_kernel(const float* __restrict__ W1s, const float* __restrict__ b1s,
                                    const float* __restrict__ W1d, const float* __restrict__ b1d,
                                    const float* __restrict__ W2s, const float* __restrict__ b2s,
                                    const float* __restrict__ W2d, const float* __restrict__ b2d,
                                    const int* __restrict__ srcW, int N) {
    int i = blockIdx.x * blockDim.x + threadIdx.x;
    if (i < N) g_deg[i] = 0;
    if (i < IN_DIM * 2 * HID) {
        int k = i / (2 * HID), c = i % (2 * HID);
        float v = (c < HID) ? W1s[k * HID + c] : W1d[k * HID + (c - HID)];
        g_Wc1[i] = tf32r(v);
    }
    if (i < 2 * HID) g_bc1[i] = (i < HID) ? b1s[i] : b1d[i - HID];
    if (i < HID * N2PAD) {
        int k = i / N2PAD, c = i % N2PAD;
        float v = (c < NCLS) ? W2s[k * NCLS + c]
                : (c < 2 * NCLS) ? W2d[k * NCLS + (c - NCLS)] : 0.f;
        g_Wc2p[i] = tf32r(v);
    }
    if (i < 2 * NCLS) g_bc2[i] = (i < NCLS) ? b2s[i] : b2d[i - NCLS];
    if (i == 0) {
        int ok64 = 1;
        #pragma unroll
        for (int q = 1; q < 16; q += 2) if (srcW[q] != 0) ok64 = 0;
        g_is64 = ok64;
    }
}

__global__ void convert_hist_kernel(const void* __restrict__ dstRaw, int E) {
    int e = blockIdx.x * blockDim.x + threadIdx.x;
    if (e >= E) return;
    int d = g_is64 ? (int)((const long long*)dstRaw)[e] : ((const int*)dstRaw)[e];
    g_dst32[e] = d;
    atomicAdd(&g_deg[d], 1);
}

// ---------------- 3-phase multi-block exclusive scan of g_deg -> g_rowptr ----------------
__global__ void scan_phase1(int N) {
    __shared__ int sh[1024];
    int t = threadIdx.x;
    int i = blockIdx.x * 1024 + t;
    int v = (i < N) ? g_deg[i] : 0;
    sh[t] = v;
    __syncthreads();
    #pragma unroll
    for (int off = 1; off < 1024; off <<= 1) {
        int x = (t >= off) ? sh[t - off] : 0;
        __syncthreads();
        sh[t] += x;
        __syncthreads();
    }
    if (i < N) g_rowptr[i] = sh[t] - v;
    if (t == 1023) g_bsum[blockIdx.x] = sh[1023];
}

__global__ void scan_phase2(int nb, int N) {
    __shared__ int sh[128];
    int t = threadIdx.x;
    int v = (t < nb) ? g_bsum[t] : 0;
    sh[t] = v;
    __syncthreads();
    #pragma unroll
    for (int off = 1; off < 128; off <<= 1) {
        int x = (t >= off) ? sh[t - off] : 0;
        __syncthreads();
        sh[t] += x;
        __syncthreads();
    }
    if (t < nb) g_bsum[t] = sh[t] - v;
    if (t == 127) g_rowptr[N] = sh[127];
}

__global__ void scan_phase3(int N) {
    int i = blockIdx.x * blockDim.x + threadIdx.x;
    if (i < N) {
        int r = g_rowptr[i] + g_bsum[i >> 10];
        g_rowptr[i] = r;
        g_cur[i] = r;
    }
}

__global__ void scatter_kernel(const void* __restrict__ srcRaw, int E) {
    int e = blockIdx.x * blockDim.x + threadIdx.x;
    if (e >= E) return;
    int s = g_is64 ? (int)((const long long*)srcRaw)[e] : ((const int*)srcRaw)[e];
    int d = g_dst32[e];
    int p = atomicAdd(&g_cur[d], 1);
    g_src_sorted[p] = s;
}

// ---------------- GEMM 1 (TF32 TC, 64x32 warp tiles, 2 CTAs/SM) ----------------
// 256 threads = 8 warps as 2(M) x 4(N); block tile 128x128; warp tile 64x32.
__global__ void __launch_bounds__(256, 2)
gemm1_tc_kernel(const float* __restrict__ x, int M) {
    __shared__ float As[128][36];
    __shared__ float Bs[32][136];
    int tid  = threadIdx.x;
    int lane = tid & 31;
    int warp = tid >> 5;
    int row0 = blockIdx.x * 128;
    int mRow = (warp >> 2) * 64;     // 0 or 64
    int nCol = (warp & 3) * 32;      // 0,32,64,96
    int gid = lane >> 2;
    int tig = lane & 3;

    float c[4][4][4];
    #pragma unroll
    for (int i = 0; i < 4; ++i)
        #pragma unroll
        for (int j = 0; j < 4; ++j)
            #pragma unroll
            for (int q = 0; q < 4; ++q) c[i][j][q] = 0.f;

    for (int chunk = 0; chunk < 8; ++chunk) {
        int k0 = chunk * 32;
        // load A tile 128x32 (float4), tf32-round at store
        #pragma unroll
        for (int i = 0; i < 4; ++i) {
            int id = tid * 4 + i;
            int r = id >> 3, q = id & 7;
            int grow = row0 + r;
            float4 v = (grow < M)
                ? *(const float4*)(x + (size_t)grow * IN_DIM + k0 + q * 4)
                : make_float4(0.f, 0.f, 0.f, 0.f);
            v.x = tf32r(v.x); v.y = tf32r(v.y); v.z = tf32r(v.z); v.w = tf32r(v.w);
            *(float4*)&As[r][q * 4] = v;
        }
        // load B tile 32x128 (float4), already tf32
        #pragma unroll
        for (int i = 0; i < 4; ++i) {
            int id = tid * 4 + i;
            int r = id >> 5, q = id & 31;
            *(float4*)&Bs[r][q * 4] = *(const float4*)&g_Wc1[(k0 + r) * 128 + q * 4];
        }
        __syncthreads();
        #pragma unroll
        for (int kk = 0; kk < 32; kk += 8) {
            uint32_t a[4][4];
            #pragma unroll
            for (int i = 0; i < 4; ++i) {
                int rr = mRow + i * 16;
                a[i][0] = __float_as_uint(As[rr + gid    ][kk + tig    ]);
                a[i][1] = __float_as_uint(As[rr + gid + 8][kk + tig    ]);
                a[i][2] = __float_as_uint(As[rr + gid    ][kk + tig + 4]);
                a[i][3] = __float_as_uint(As[rr + gid + 8][kk + tig + 4]);
            }
            #pragma unroll
            for (int j = 0; j < 4; ++j) {
                uint32_t b[2];
                b[0] = __float_as_uint(Bs[kk + tig    ][nCol + j * 8 + gid]);
                b[1] = __float_as_uint(Bs[kk + tig + 4][nCol + j * 8 + gid]);
                #pragma unroll
                for (int i = 0; i < 4; ++i) {
                    asm("mma.sync.aligned.m16n8k8.row.col.f32.tf32.tf32.f32 "
                        "{%0,%1,%2,%3}, {%4,%5,%6,%7}, {%8,%9}, {%0,%1,%2,%3};"
                        : "+f"(c[i][j][0]), "+f"(c[i][j][1]), "+f"(c[i][j][2]), "+f"(c[i][j][3])
                        : "r"(a[i][0]), "r"(a[i][1]), "r"(a[i][2]), "r"(a[i][3]),
                          "r"(b[0]), "r"(b[1]));
                }
            }
        }
        __syncthreads();
    }
    #pragma unroll
    for (int i = 0; i < 4; ++i) {
        int r0 = row0 + mRow + i * 16 + gid;
        int r1 = r0 + 8;
        #pragma unroll
        for (int j = 0; j < 4; ++j) {
            int cb = nCol + j * 8 + tig * 2;
            float2 bv = *(const float2*)&g_bc1[cb];
            if (r0 < M) {
                float2 v = make_float2(c[i][j][0] + bv.x, c[i][j][1] + bv.y);
                if (cb < HID) *(float2*)&g_fs1[(size_t)r0 * HID + cb] = v;
                else          *(float2*)&g_fd1[(size_t)r0 * HID + cb - HID] = v;
            }
            if (r1 < M) {
                float2 v = make_float2(c[i][j][2] + bv.x, c[i][j][3] + bv.y);
                if (cb < HID) *(float2*)&g_fs1[(size_t)r1 * HID + cb] = v;
                else          *(float2*)&g_fd1[(size_t)r1 * HID + cb - HID] = v;
            }
        }
    }
}

// ---------------- GEMM 2 (TF32 TC): h[M,64] @ Wc2p[64,96] -> fs2|fd2 (stride 48) ----------------
__device__ __forceinline__ void g2_store(int row, int c, float v) {
    if (c >= 2 * NCLS) return;
    v += g_bc2[c];
    if (c < NCLS) g_fs2[(size_t)row * NC2P + c] = v;
    else          g_fd2[(size_t)row * NC2P + (c - NCLS)] = v;
}

__global__ void gemm2_tc_kernel(int M) {
    __shared__ float As[128][36];
    __shared__ float Bs[32][104];
    int tid  = threadIdx.x;
    int lane = tid & 31;
    int warp = tid >> 5;
    int row0 = blockIdx.x * 128;
    int warpRow = warp * 16;
    int gid = lane >> 2;
    int tig = lane & 3;

    float c[12][4];
    #pragma unroll
    for (int j = 0; j < 12; ++j)
        #pragma unroll
        for (int q = 0; q < 4; ++q) c[j][q] = 0.f;

    float4 ra[4], rb[3];
    #pragma unroll
    for (int i = 0; i < 4; ++i) {
        int id = tid * 4 + i;
        int r = id >> 3, q = id & 7;
        int grow = row0 + r;
        ra[i] = (grow < M) ? *(const float4*)(g_h + (size_t)grow * HID + q * 4)
                           : make_float4(0.f, 0.f, 0.f, 0.f);
    }
    #pragma unroll
    for (int i = 0; i < 3; ++i) {
        int id = tid + i * 256;
        int r = id / 24, q = id % 24;
        rb[i] = *(const float4*)&g_Wc2p[r * N2PAD + q * 4];
    }

    #pragma unroll
    for (int chunk = 0; chunk < 2; ++chunk) {
        #pragma unroll
        for (int i = 0; i < 4; ++i) {
            int id = tid * 4 + i;
            int r = id >> 3, q = id & 7;
            float4 v = ra[i];
            v.x = tf32r(v.x); v.y = tf32r(v.y); v.z = tf32r(v.z); v.w = tf32r(v.w);
            *(float4*)&As[r][q * 4] = v;
        }
        #pragma unroll
        for (int i = 0; i < 3; ++i) {
            int id = tid + i * 256;
            int r = id / 24, q = id % 24;
            *(float4*)&Bs[r][q * 4] = rb[i];
        }
        __syncthreads();
        if (chunk == 0) {
            #pragma unroll
            for (int i = 0; i < 4; ++i) {
                int id = tid * 4 + i;
                int r = id >> 3, q = id & 7;
                int grow = row0 + r;
                ra[i] = (grow < M) ? *(const float4*)(g_h + (size_t)grow * HID + 32 + q * 4)
                                   : make_float4(0.f, 0.f, 0.f, 0.f);
            }
            #pragma unroll
            for (int i = 0; i < 3; ++i) {
                int id = tid + i * 256;
                int r = id / 24, q = id % 24;
                rb[i] = *(const float4*)&g_Wc2p[(32 + r) * N2PAD + q * 4];
            }
        }
        #pragma unroll
        for (int kk = 0; kk < 32; kk += 8) {
            uint32_t a[4];
            a[0] = __float_as_uint(As[warpRow + gid    ][kk + tig    ]);
            a[1] = __float_as_uint(As[warpRow + gid + 8][kk + tig    ]);
            a[2] = __float_as_uint(As[warpRow + gid    ][kk + tig + 4]);
            a[3] = __float_as_uint(As[warpRow + gid + 8][kk + tig + 4]);
            #pragma unroll
            for (int j = 0; j < 12; ++j) {
                uint32_t b[2];
                b[0] = __float_as_uint(Bs[kk + tig    ][j * 8 + gid]);
                b[1] = __float_as_uint(Bs[kk + tig + 4][j * 8 + gid]);
                asm("mma.sync.aligned.m16n8k8.row.col.f32.tf32.tf32.f32 "
                    "{%0,%1,%2,%3}, {%4,%5,%6,%7}, {%8,%9}, {%0,%1,%2,%3};"
                    : "+f"(c[j][0]), "+f"(c[j][1]), "+f"(c[j][2]), "+f"(c[j][3])
                    : "r"(a[0]), "r"(a[1]), "r"(a[2]), "r"(a[3]),
                      "r"(b[0]), "r"(b[1]));
            }
        }
        __syncthreads();
    }
    int r0 = row0 + warpRow + gid;
    int r1 = r0 + 8;
    #pragma unroll
    for (int j = 0; j < 12; ++j) {
        int cb = j * 8 + tig * 2;
        if (r0 < M) { g2_store(r0, cb, c[j][0]); g2_store(r0, cb + 1, c[j][1]); }
        if (r1 < M) { g2_store(r1, cb, c[j][2]); g2_store(r1, cb + 1, c[j][3]); }
    }
}

// ---------------- layer 1: HALF-warp per node, 4 dims/lane (float4), head = 2 lanes ----------------
__global__ void layer1_kernel(int N, const float* __restrict__ attn1,
                              const float* __restrict__ bias1) {
    int gwarp = (blockIdx.x * blockDim.x + threadIdx.x) >> 5;
    int lane  = threadIdx.x & 31;
    int half  = lane >> 4;                   // 0 or 1
    int l16   = lane & 15;
    int w     = gwarp * 2 + half;
    if (w >= N) return;
    unsigned hmask = half ? 0xFFFF0000u : 0x0000FFFFu;
    int start = g_rowptr[w], end = g_rowptr[w + 1];
    int j0 = 4 * l16;                        // dims j0..j0+3 (head = l16>>1)

    float4 bv = *(const float4*)&bias1[j0];
    if (start == end) {
        float4 o = make_float4(elu(bv.x), elu(bv.y), elu(bv.z), elu(bv.w));
        *(float4*)&g_h[(size_t)w * HID + j0] = o;
        return;
    }
    float4 fdv = *(const float4*)&g_fd1[(size_t)w * HID + j0];
    float4 att = *(const float4*)&attn1[j0];

    float mx = -INFINITY, s = 0.f;
    float ax = 0.f, ay = 0.f, az = 0.f, aw = 0.f;

    for (int p = start; p < end; ++p) {
        int u = g_src_sorted[p];
        float4 f = *(const float4*)&g_fs1[(size_t)u * HID + j0];
        float t = lrelu(f.x + fdv.x) * att.x + lrelu(f.y + fdv.y) * att.y
                + lrelu(f.z + fdv.z) * att.z + lrelu(f.w + fdv.w) * att.w;
        t += __shfl_xor_sync(hmask, t, 1);   // head score (2 lanes per head)
        float ed = __expf(0.f - fabsf(t - mx));
        bool up = t > mx;
        float sc = up ? ed : 1.f;
        float wt = up ? 1.f : ed;
        mx = fmaxf(mx, t);
        s = fmaf(s, sc, wt);
        ax = fmaf(ax, sc, wt * f.x);
        ay = fmaf(ay, sc, wt * f.y);
        az = fmaf(az, sc, wt * f.z);
        aw = fmaf(aw, sc, wt * f.w);
    }
    float inv = 1.f / s;
    float4 o = make_float4(elu(ax * inv + bv.x), elu(ay * inv + bv.y),
                           elu(az * inv + bv.z), elu(aw * inv + bv.w));
    *(float4*)&g_h[(size_t)w * HID + j0] = o;
}

// ---------------- layer 2: warp/node, 2 classes per lane (padded stride 48) ----------------
__global__ void layer2_kernel(int N, const float* __restrict__ attn2,
                              const float* __restrict__ bias2,
                              float* __restrict__ out) {
    int w = (blockIdx.x * blockDim.x + threadIdx.x) >> 5;
    int lane = threadIdx.x & 31;
    if (w >= N) return;
    int start = g_rowptr[w], end = g_rowptr[w + 1];
    int j0 = 2 * lane;
    int off = j0 < 46 ? j0 : 46;                     // clamped, even -> aligned float2
    bool m0 = (j0 < NCLS), m1 = (j0 + 1 < NCLS);

    float b0 = m0 ? bias2[j0] : 0.f;
    float b1 = m1 ? bias2[j0 + 1] : 0.f;
    if (start == end) {
        if (m0) out[(size_t)w * NCLS + j0] = b0;
        if (m1) out[(size_t)w * NCLS + j0 + 1] = b1;
        return;
    }
    float2 fdr = *(const float2*)&g_fd2[(size_t)w * NC2P + off];
    float fdv0 = m0 ? fdr.x : 0.f;
    float fdv1 = m1 ? fdr.y : 0.f;
    float att0 = m0 ? attn2[j0] : 0.f;
    float att1 = m1 ? attn2[j0 + 1] : 0.f;

    float mx = -INFINITY, s = 0.f;
    float acc0 = 0.f, acc1 = 0.f;

    for (int p = start; p < end; ++p) {
        int u = g_src_sorted[p];
        float2 fr = *(const float2*)&g_fs2[(size_t)u * NC2P + off];
        float f0 = m0 ? fr.x : 0.f;
        float f1 = m1 ? fr.y : 0.f;
        float t = lrelu(f0 + fdv0) * att0 + lrelu(f1 + fdv1) * att1;
        t += __shfl_xor_sync(0xffffffffu, t, 1);
        t += __shfl_xor_sync(0xffffffffu, t, 2);
        t += __shfl_xor_sync(0xffffffffu, t, 4);
        t += __shfl_xor_sync(0xffffffffu, t, 8);
        t += __shfl_xor_sync(0xffffffffu, t, 16);
        float ed = __expf(0.f - fabsf(t - mx));
        bool up = t > mx;
        float sc = up ? ed : 1.f;
        float wt = up ? 1.f : ed;
        mx = fmaxf(mx, t);
        s = fmaf(s, sc, wt);
        acc0 = fmaf(acc0, sc, wt * f0);
        acc1 = fmaf(acc1, sc, wt * f1);
    }
    float inv = 1.f / s;
    if (m0) out[(size_t)w * NCLS + j0]     = acc0 * inv + b0;
    if (m1) out[(size_t)w * NCLS + j0 + 1] = acc1 * inv + b1;
}

// ---------------- launch ----------------
extern "C" void kernel_launch(void* const* d_in, const int* in_sizes, int n_in,
                              void* d_out, int out_size) {
    const float* x      = (const float*)d_in[0];
    const void*  srcRaw = d_in[1];
    const void*  dstRaw = d_in[2];
    const float* W1s = (const float*)d_in[3];
    const float* b1s = (const float*)d_in[4];
    const float* W1d = (const float*)d_in[5];
    const float* b1d = (const float*)d_in[6];
    const float* attn1 = (const float*)d_in[7];
    const float* bias1 = (const float*)d_in[8];
    const float* W2s = (const float*)d_in[9];
    const float* b2s = (const float*)d_in[10];
    const float* W2d = (const float*)d_in[11];
    const float* b2d = (const float*)d_in[12];
    const float* attn2 = (const float*)d_in[13];
    const float* bias2 = (const float*)d_in[14];
    float* out = (float*)d_out;

    int N = in_sizes[0] / IN_DIM;   // 100000
    int E = in_sizes[1];            // 1600000
    int nb = (N + 1023) >> 10;      // scan blocks (98)

    // #1: fused combine + zero_deg + detect (covers N range)
    combine_zero_kernel<<<(N + 255) / 256, 256>>>(W1s, b1s, W1d, b1d,
                                                  W2s, b2s, W2d, b2d,
                                                  (const int*)srcRaw, N);
    // #2
    convert_hist_kernel<<<(E + 255) / 256, 256>>>(dstRaw, E);
    // #3
    scan_phase1<<<nb, 1024>>>(N);
    // #4  <- ncu-captured launch: gemm1 (independent of scan chain)
    gemm1_tc_kernel<<<(N + 127) / 128, 256>>>(x, N);
    // #5..#7: finish CSR build
    scan_phase2<<<1, 128>>>(nb, N);
    scan_phase3<<<(N + 255) / 256, 256>>>(N);
    scatter_kernel<<<(E + 255) / 256, 256>>>(srcRaw, E);
    // #8..#10
    layer1_kernel<<<(N + 15) / 16, 256>>>(N, attn1, bias1);
    gemm2_tc_kernel<<<(N + 127) / 128, 256>>>(N);
    layer2_kernel<<<(N + 7) / 8, 256>>>(N, attn2, bias2, out);
}

// round 15
// speedup vs baseline: 1.1771x; 1.1076x over previous
#include <cuda_runtime.h>
#include <cuda_bf16.h>
#include <cuda_fp16.h>
#include <math.h>
#include <stdint.h>

// Problem constants (fixed instance)
#define NMAX   100000
#define EMAX   1600000
#define IN_DIM 256
#define HID    64      // HEADS*D1 = 8*8
#define HEADS  8
#define D1     8
#define NCLS   47
#define NC2P   48      // padded stride for layer-2 feature arrays
#define N2PAD  96      // padded output cols for gemm2 (2*47 -> 96)
#define NEG_SLOPE 0.2f
#define ASTR   40      // smem half-stride for gemm1 tiles (bank-conflict-free)

// ---------------- device scratch (static allocation; no cudaMalloc) ----------------
__device__ int   g_is64;
__device__ int   g_dst32[EMAX];
__device__ int   g_src_sorted[EMAX];
__device__ int   g_deg[NMAX];
__device__ int   g_rowptr[NMAX + 1];
__device__ int   g_cur[NMAX];
__device__ int   g_bsum[128];           // >= ceil(NMAX/1024)=98 block sums

__device__ float g_fs1[(size_t)NMAX * HID];
__device__ float g_fd1[(size_t)NMAX * HID];
__device__ float g_h  [(size_t)NMAX * HID];
__device__ float g_fs2[(size_t)NMAX * NC2P];
__device__ float g_fd2[(size_t)NMAX * NC2P];

__device__ __half g_Wc1h[128 * 256];            // [n=128][k=256] fp16, n-major
__device__ float  g_bc1[2 * HID];
__device__ float  g_Wc2p[HID * N2PAD];          // [64][96], tf32, cols 94-95 zero
__device__ float  g_bc2[2 * NCLS];

__device__ __forceinline__ float lrelu(float x) { return x > 0.f ? x : NEG_SLOPE * x; }
__device__ __forceinline__ float elu(float x)   { return x > 0.f ? x : expm1f(x); }
__device__ __forceinline__ float tf32r(float x) {
    uint32_t r; asm("cvt.rna.tf32.f32 %0, %1;" : "=r"(r) : "f"(x));
    return __uint_as_float(r);
}

// ---------------- fused: weight packing + deg zero + index dtype detection ----------------
__global__ void combine_zero_kernel(const float* __restrict__ W1s, const float* __restrict__ b1s,
                                    const float* __restrict__ W1d, const float* __restrict__ b1d,
                                    const float* __restrict__ W2s, const float* __restrict__ b2s,
                                    const float* __restrict__ W2d, const float* __restrict__ b2d,
                                    const int* __restrict__ srcW, int N) {
    int i = blockIdx.x * blockDim.x + threadIdx.x;
    if (i < N) g_deg[i] = 0;
    // pack W1 transposed (n-major) as fp16
    if (i < 128 * 256) {
        int n = i >> 8, k = i & 255;
        float v = (n < HID) ? W1s[k * HID + n] : W1d[k * HID + (n - HID)];
        g_Wc1h[i] = __float2half_rn(v);
    }
    if (i < 2 * HID) g_bc1[i] = (i < HID) ? b1s[i] : b1d[i - HID];
    if (i < HID * N2PAD) {
        int k = i / N2PAD, c = i % N2PAD;
        float v = (c < NCLS) ? W2s[k * NCLS + c]
                : (c < 2 * NCLS) ? W2d[k * NCLS + (c - NCLS)] : 0.f;
        g_Wc2p[i] = tf32r(v);
    }
    if (i < 2 * NCLS) g_bc2[i] = (i < NCLS) ? b2s[i] : b2d[i - NCLS];
    if (i == 0) {
        int ok64 = 1;
        #pragma unroll
        for (int q = 1; q < 16; q += 2) if (srcW[q] != 0) ok64 = 0;
        g_is64 = ok64;
    }
}

__global__ void convert_hist_kernel(const void* __restrict__ dstRaw, int E) {
    int e = blockIdx.x * blockDim.x + threadIdx.x;
    if (e >= E) return;
    int d = g_is64 ? (int)((const long long*)dstRaw)[e] : ((const int*)dstRaw)[e];
    g_dst32[e] = d;
    atomicAdd(&g_deg[d], 1);
}

// ---------------- 3-phase multi-block exclusive scan of g_deg -> g_rowptr ----------------
__global__ void scan_phase1(int N) {
    __shared__ int sh[1024];
    int t = threadIdx.x;
    int i = blockIdx.x * 1024 + t;
    int v = (i < N) ? g_deg[i] : 0;
    sh[t] = v;
    __syncthreads();
    #pragma unroll
    for (int off = 1; off < 1024; off <<= 1) {
        int x = (t >= off) ? sh[t - off] : 0;
        __syncthreads();
        sh[t] += x;
        __syncthreads();
    }
    if (i < N) g_rowptr[i] = sh[t] - v;
    if (t == 1023) g_bsum[blockIdx.x] = sh[1023];
}

__global__ void scan_phase2(int nb, int N) {
    __shared__ int sh[128];
    int t = threadIdx.x;
    int v = (t < nb) ? g_bsum[t] : 0;
    sh[t] = v;
    __syncthreads();
    #pragma unroll
    for (int off = 1; off < 128; off <<= 1) {
        int x = (t >= off) ? sh[t - off] : 0;
        __syncthreads();
        sh[t] += x;
        __syncthreads();
    }
    if (t < nb) g_bsum[t] = sh[t] - v;
    if (t == 127) g_rowptr[N] = sh[127];
}

__global__ void scan_phase3(int N) {
    int i = blockIdx.x * blockDim.x + threadIdx.x;
    if (i < N) {
        int r = g_rowptr[i] + g_bsum[i >> 10];
        g_rowptr[i] = r;
        g_cur[i] = r;
    }
}

__global__ void scatter_kernel(const void* __restrict__ srcRaw, int E) {
    int e = blockIdx.x * blockDim.x + threadIdx.x;
    if (e >= E) return;
    int s = g_is64 ? (int)((const long long*)srcRaw)[e] : ((const int*)srcRaw)[e];
    int d = g_dst32[e];
    int p = atomicAdd(&g_cur[d], 1);
    g_src_sorted[p] = s;
}

// ---------------- GEMM 1 (FP16 HMMA m16n8k16, 64x32 warp tiles, 2 CTAs/SM) ----------------
// 256 threads = 8 warps as 2(M) x 4(N); block tile 128x128; K chunked by 32.
__global__ void __launch_bounds__(256, 2)
gemm1_tc_kernel(const float* __restrict__ x, int M) {
    __shared__ __align__(16) __half Ash[128 * ASTR];   // [row][k] halves
    __shared__ __align__(16) __half Bsh[128 * ASTR];   // [n][k] halves
    int tid  = threadIdx.x;
    int lane = tid & 31;
    int warp = tid >> 5;
    int row0 = blockIdx.x * 128;
    int mRow = (warp >> 2) * 64;     // 0 or 64
    int nCol = (warp & 3) * 32;      // 0,32,64,96
    int gid = lane >> 2;
    int tig = lane & 3;

    float c[4][4][4];
    #pragma unroll
    for (int i = 0; i < 4; ++i)
        #pragma unroll
        for (int j = 0; j < 4; ++j)
            #pragma unroll
            for (int q = 0; q < 4; ++q) c[i][j][q] = 0.f;

    for (int chunk = 0; chunk < 8; ++chunk) {
        int k0 = chunk * 32;
        // A tile: 128 rows x 32 k-halves (convert fp32->fp16 at store)
        #pragma unroll
        for (int i = 0; i < 4; ++i) {
            int id = tid * 4 + i;
            int r = id >> 3, q = id & 7;
            int grow = row0 + r;
            float4 v = (grow < M)
                ? *(const float4*)(x + (size_t)grow * IN_DIM + k0 + q * 4)
                : make_float4(0.f, 0.f, 0.f, 0.f);
            __half2 h01 = __floats2half2_rn(v.x, v.y);
            __half2 h23 = __floats2half2_rn(v.z, v.w);
            *(__half2*)&Ash[r * ASTR + q * 4]     = h01;
            *(__half2*)&Ash[r * ASTR + q * 4 + 2] = h23;
        }
        // B tile: copy 128 n-rows x 32 k-halves from prepacked fp16
        {
            int n = tid >> 1, part = (tid & 1) * 16;
            const uint4* src = (const uint4*)&g_Wc1h[n * 256 + k0 + part];
            uint4 v0 = src[0];
            uint4 v1 = src[1];
            *(uint4*)&Bsh[n * ASTR + part]     = v0;
            *(uint4*)&Bsh[n * ASTR + part + 8] = v1;
        }
        __syncthreads();
        #pragma unroll
        for (int kb = 0; kb < 32; kb += 16) {
            uint32_t a[4][4];
            #pragma unroll
            for (int i = 0; i < 4; ++i) {
                int rr = mRow + i * 16;
                a[i][0] = *(const uint32_t*)&Ash[(rr + gid)     * ASTR + kb + tig * 2];
                a[i][1] = *(const uint32_t*)&Ash[(rr + gid + 8) * ASTR + kb + tig * 2];
                a[i][2] = *(const uint32_t*)&Ash[(rr + gid)     * ASTR + kb + tig * 2 + 8];
                a[i][3] = *(const uint32_t*)&Ash[(rr + gid + 8) * ASTR + kb + tig * 2 + 8];
            }
            #pragma unroll
            for (int j = 0; j < 4; ++j) {
                int n = nCol + j * 8 + gid;
                uint32_t b0 = *(const uint32_t*)&Bsh[n * ASTR + kb + tig * 2];
                uint32_t b1 = *(const uint32_t*)&Bsh[n * ASTR + kb + tig * 2 + 8];
                #pragma unroll
                for (int i = 0; i < 4; ++i) {
                    asm("mma.sync.aligned.m16n8k16.row.col.f32.f16.f16.f32 "
                        "{%0,%1,%2,%3}, {%4,%5,%6,%7}, {%8,%9}, {%0,%1,%2,%3};"
                        : "+f"(c[i][j][0]), "+f"(c[i][j][1]), "+f"(c[i][j][2]), "+f"(c[i][j][3])
                        : "r"(a[i][0]), "r"(a[i][1]), "r"(a[i][2]), "r"(a[i][3]),
                          "r"(b0), "r"(b1));
                }
            }
        }
        __syncthreads();
    }
    #pragma unroll
    for (int i = 0; i < 4; ++i) {
        int r0 = row0 + mRow + i * 16 + gid;
        int r1 = r0 + 8;
        #pragma unroll
        for (int j = 0; j < 4; ++j) {
            int cb = nCol + j * 8 + tig * 2;
            float2 bv = *(const float2*)&g_bc1[cb];
            if (r0 < M) {
                float2 v = make_float2(c[i][j][0] + bv.x, c[i][j][1] + bv.y);
                if (cb < HID) *(float2*)&g_fs1[(size_t)r0 * HID + cb] = v;
                else          *(float2*)&g_fd1[(size_t)r0 * HID + cb - HID] = v;
            }
            if (r1 < M) {
                float2 v = make_float2(c[i][j][2] + bv.x, c[i][j][3] + bv.y);
                if (cb < HID) *(float2*)&g_fs1[(size_t)r1 * HID + cb] = v;
                else          *(float2*)&g_fd1[(size_t)r1 * HID + cb - HID] = v;
            }
        }
    }
}

// ---------------- GEMM 2 (TF32 mma.sync): h[M,64] @ Wc2p[64,96] -> fs2|fd2 ----------------
__device__ __forceinline__ void g2_store(int row, int c, float v) {
    if (c >= 2 * NCLS) return;
    v += g_bc2[c];
    if (c < NCLS) g_fs2[(size_t)row * NC2P + c] = v;
    else          g_fd2[(size_t)row * NC2P + (c - NCLS)] = v;
}

__global__ void gemm2_tc_kernel(int M) {
    __shared__ float As[128][36];
    __shared__ float Bs[32][104];
    int tid  = threadIdx.x;
    int lane = tid & 31;
    int warp = tid >> 5;
    int row0 = blockIdx.x * 128;
    int warpRow = warp * 16;
    int gid = lane >> 2;
    int tig = lane & 3;

    float c[12][4];
    #pragma unroll
    for (int j = 0; j < 12; ++j)
        #pragma unroll
        for (int q = 0; q < 4; ++q) c[j][q] = 0.f;

    float4 ra[4], rb[3];
    #pragma unroll
    for (int i = 0; i < 4; ++i) {
        int id = tid * 4 + i;
        int r = id >> 3, q = id & 7;
        int grow = row0 + r;
        ra[i] = (grow < M) ? *(const float4*)(g_h + (size_t)grow * HID + q * 4)
                           : make_float4(0.f, 0.f, 0.f, 0.f);
    }
    #pragma unroll
    for (int i = 0; i < 3; ++i) {
        int id = tid + i * 256;
        int r = id / 24, q = id % 24;
        rb[i] = *(const float4*)&g_Wc2p[r * N2PAD + q * 4];
    }

    #pragma unroll
    for (int chunk = 0; chunk < 2; ++chunk) {
        #pragma unroll
        for (int i = 0; i < 4; ++i) {
            int id = tid * 4 + i;
            int r = id >> 3, q = id & 7;
            float4 v = ra[i];
            v.x = tf32r(v.x); v.y = tf32r(v.y); v.z = tf32r(v.z); v.w = tf32r(v.w);
            *(float4*)&As[r][q * 4] = v;
        }
        #pragma unroll
        for (int i = 0; i < 3; ++i) {
            int id = tid + i * 256;
            int r = id / 24, q = id % 24;
            *(float4*)&Bs[r][q * 4] = rb[i];
        }
        __syncthreads();
        if (chunk == 0) {
            #pragma unroll
            for (int i = 0; i < 4; ++i) {
                int id = tid * 4 + i;
                int r = id >> 3, q = id & 7;
                int grow = row0 + r;
                ra[i] = (grow < M) ? *(const float4*)(g_h + (size_t)grow * HID + 32 + q * 4)
                                   : make_float4(0.f, 0.f, 0.f, 0.f);
            }
            #pragma unroll
            for (int i = 0; i < 3; ++i) {
                int id = tid + i * 256;
                int r = id / 24, q = id % 24;
                rb[i] = *(const float4*)&g_Wc2p[(32 + r) * N2PAD + q * 4];
            }
        }
        #pragma unroll
        for (int kk = 0; kk < 32; kk += 8) {
            uint32_t a[4];
            a[0] = __float_as_uint(As[warpRow + gid    ][kk + tig    ]);
            a[1] = __float_as_uint(As[warpRow + gid + 8][kk + tig    ]);
            a[2] = __float_as_uint(As[warpRow + gid    ][kk + tig + 4]);
            a[3] = __float_as_uint(As[warpRow + gid + 8][kk + tig + 4]);
            #pragma unroll
            for (int j = 0; j < 12; ++j) {
                uint32_t b[2];
                b[0] = __float_as_uint(Bs[kk + tig    ][j * 8 + gid]);
                b[1] = __float_as_uint(Bs[kk + tig + 4][j * 8 + gid]);
                asm("mma.sync.aligned.m16n8k8.row.col.f32.tf32.tf32.f32 "
                    "{%0,%1,%2,%3}, {%4,%5,%6,%7}, {%8,%9}, {%0,%1,%2,%3};"
                    : "+f"(c[j][0]), "+f"(c[j][1]), "+f"(c[j][2]), "+f"(c[j][3])
                    : "r"(a[0]), "r"(a[1]), "r"(a[2]), "r"(a[3]),
                      "r"(b[0]), "r"(b[1]));
            }
        }
        __syncthreads();
    }
    int r0 = row0 + warpRow + gid;
    int r1 = r0 + 8;
    #pragma unroll
    for (int j = 0; j < 12; ++j) {
        int cb = j * 8 + tig * 2;
        if (r0 < M) { g2_store(r0, cb, c[j][0]); g2_store(r0, cb + 1, c[j][1]); }
        if (r1 < M) { g2_store(r1, cb, c[j][2]); g2_store(r1, cb + 1, c[j][3]); }
    }
}

// ---------------- layer 1: HALF-warp per node, 4 dims/lane (float4), head = 2 lanes ----------------
__global__ void layer1_kernel(int N, const float* __restrict__ attn1,
                              const float* __restrict__ bias1) {
    int gwarp = (blockIdx.x * blockDim.x + threadIdx.x) >> 5;
    int lane  = threadIdx.x & 31;
    int half  = lane >> 4;                   // 0 or 1
    int l16   = lane & 15;
    int w     = gwarp * 2 + half;
    if (w >= N) return;
    unsigned hmask = half ? 0xFFFF0000u : 0x0000FFFFu;
    int start = g_rowptr[w], end = g_rowptr[w + 1];
    int j0 = 4 * l16;                        // dims j0..j0+3 (head = l16>>1)

    float4 bv = *(const float4*)&bias1[j0];
    if (start == end) {
        float4 o = make_float4(elu(bv.x), elu(bv.y), elu(bv.z), elu(bv.w));
        *(float4*)&g_h[(size_t)w * HID + j0] = o;
        return;
    }
    float4 fdv = *(const float4*)&g_fd1[(size_t)w * HID + j0];
    float4 att = *(const float4*)&attn1[j0];

    float mx = -INFINITY, s = 0.f;
    float ax = 0.f, ay = 0.f, az = 0.f, aw = 0.f;

    for (int p = start; p < end; ++p) {
        int u = g_src_sorted[p];
        float4 f = *(const float4*)&g_fs1[(size_t)u * HID + j0];
        float t = lrelu(f.x + fdv.x) * att.x + lrelu(f.y + fdv.y) * att.y
                + lrelu(f.z + fdv.z) * att.z + lrelu(f.w + fdv.w) * att.w;
        t += __shfl_xor_sync(hmask, t, 1);   // head score (2 lanes per head)
        float ed = __expf(0.f - fabsf(t - mx));
        bool up = t > mx;
        float sc = up ? ed : 1.f;
        float wt = up ? 1.f : ed;
        mx = fmaxf(mx, t);
        s = fmaf(s, sc, wt);
        ax = fmaf(ax, sc, wt * f.x);
        ay = fmaf(ay, sc, wt * f.y);
        az = fmaf(az, sc, wt * f.z);
        aw = fmaf(aw, sc, wt * f.w);
    }
    float inv = 1.f / s;
    float4 o = make_float4(elu(ax * inv + bv.x), elu(ay * inv + bv.y),
                           elu(az * inv + bv.z), elu(aw * inv + bv.w));
    *(float4*)&g_h[(size_t)w * HID + j0] = o;
}

// ---------------- layer 2: warp/node, 2 classes per lane (padded stride 48) ----------------
__global__ void layer2_kernel(int N, const float* __restrict__ attn2,
                              const float* __restrict__ bias2,
                              float* __restrict__ out) {
    int w = (blockIdx.x * blockDim.x + threadIdx.x) >> 5;
    int lane = threadIdx.x & 31;
    if (w >= N) return;
    int start = g_rowptr[w], end = g_rowptr[w + 1];
    int j0 = 2 * lane;
    int off = j0 < 46 ? j0 : 46;                     // clamped, even -> aligned float2
    bool m0 = (j0 < NCLS), m1 = (j0 + 1 < NCLS);

    float b0 = m0 ? bias2[j0] : 0.f;
    float b1 = m1 ? bias2[j0 + 1] : 0.f;
    if (start == end) {
        if (m0) out[(size_t)w * NCLS + j0] = b0;
        if (m1) out[(size_t)w * NCLS + j0 + 1] = b1;
        return;
    }
    float2 fdr = *(const float2*)&g_fd2[(size_t)w * NC2P + off];
    float fdv0 = m0 ? fdr.x : 0.f;
    float fdv1 = m1 ? fdr.y : 0.f;
    float att0 = m0 ? attn2[j0] : 0.f;
    float att1 = m1 ? attn2[j0 + 1] : 0.f;

    float mx = -INFINITY, s = 0.f;
    float acc0 = 0.f, acc1 = 0.f;

    for (int p = start; p < end; ++p) {
        int u = g_src_sorted[p];
        float2 fr = *(const float2*)&g_fs2[(size_t)u * NC2P + off];
        float f0 = m0 ? fr.x : 0.f;
        float f1 = m1 ? fr.y : 0.f;
        float t = lrelu(f0 + fdv0) * att0 + lrelu(f1 + fdv1) * att1;
        t += __shfl_xor_sync(0xffffffffu, t, 1);
        t += __shfl_xor_sync(0xffffffffu, t, 2);
        t += __shfl_xor_sync(0xffffffffu, t, 4);
        t += __shfl_xor_sync(0xffffffffu, t, 8);
        t += __shfl_xor_sync(0xffffffffu, t, 16);
        float ed = __expf(0.f - fabsf(t - mx));
        bool up = t > mx;
        float sc = up ? ed : 1.f;
        float wt = up ? 1.f : ed;
        mx = fmaxf(mx, t);
        s = fmaf(s, sc, wt);
        acc0 = fmaf(acc0, sc, wt * f0);
        acc1 = fmaf(acc1, sc, wt * f1);
    }
    float inv = 1.f / s;
    if (m0) out[(size_t)w * NCLS + j0]     = acc0 * inv + b0;
    if (m1) out[(size_t)w * NCLS + j0 + 1] = acc1 * inv + b1;
}

// ---------------- launch ----------------
extern "C" void kernel_launch(void* const* d_in, const int* in_sizes, int n_in,
                              void* d_out, int out_size) {
    const float* x      = (const float*)d_in[0];
    const void*  srcRaw = d_in[1];
    const void*  dstRaw = d_in[2];
    const float* W1s = (const float*)d_in[3];
    const float* b1s = (const float*)d_in[4];
    const float* W1d = (const float*)d_in[5];
    const float* b1d = (const float*)d_in[6];
    const float* attn1 = (const float*)d_in[7];
    const float* bias1 = (const float*)d_in[8];
    const float* W2s = (const float*)d_in[9];
    const float* b2s = (const float*)d_in[10];
    const float* W2d = (const float*)d_in[11];
    const float* b2d = (const float*)d_in[12];
    const float* attn2 = (const float*)d_in[13];
    const float* bias2 = (const float*)d_in[14];
    float* out = (float*)d_out;

    int N = in_sizes[0] / IN_DIM;   // 100000
    int E = in_sizes[1];            // 1600000
    int nb = (N + 1023) >> 10;      // scan blocks (98)

    // #1: fused combine + zero_deg + detect
    combine_zero_kernel<<<(N + 255) / 256, 256>>>(W1s, b1s, W1d, b1d,
                                                  W2s, b2s, W2d, b2d,
                                                  (const int*)srcRaw, N);
    // #2
    convert_hist_kernel<<<(E + 255) / 256, 256>>>(dstRaw, E);
    // #3
    scan_phase1<<<nb, 1024>>>(N);
    // #4  <- ncu-captured launch: gemm1 (fp16 HMMA)
    gemm1_tc_kernel<<<(N + 127) / 128, 256>>>(x, N);
    // #5..#7: finish CSR build
    scan_phase2<<<1, 128>>>(nb, N);
    scan_phase3<<<(N + 255) / 256, 256>>>(N);
    scatter_kernel<<<(E + 255) / 256, 256>>>(srcRaw, E);
    // #8..#10
    layer1_kernel<<<(N + 15) / 16, 256>>>(N, attn1, bias1);
    gemm2_tc_kernel<<<(N + 127) / 128, 256>>>(N);
    layer2_kernel<<<(N + 7) / 8, 256>>>(N, attn2, bias2, out);
}